// round 17
// baseline (speedup 1.0000x reference)
#include <cuda_runtime.h>
#include <cuda_bf16.h>

// Problem constants
#define BATCH   2
#define SEQ     2048
#define DMODEL  1024
#define NHEAD   16
#define DK      64
#define MROWS   (BATCH * SEQ)       // 4096
#define DM2     (DMODEL / 2)        // u32 (16-bit pair) per row
#define WU4     (DMODEL * DMODEL / 8)  // uint4 per weight matrix (131072)

// ---------------------------------------------------------------------------
// Scratch: Q/K/V/X fp16; all four weights fp16
// ---------------------------------------------------------------------------
__device__ unsigned g_Qf[MROWS * DM2];
__device__ unsigned g_Kf[MROWS * DM2];
__device__ unsigned g_Vf[MROWS * DM2];
__device__ unsigned g_Xf[MROWS * DM2];
__device__ unsigned g_Wf[4 * DMODEL * DM2];   // fp16 wq/wk/wv/wo

// ---------------------------------------------------------------------------
// Warp-level tensor core helpers (sm_80-baseline PTX: works on plain sm_103)
// ---------------------------------------------------------------------------
__device__ __forceinline__ unsigned smem_u32(const void* p) {
    return (unsigned)__cvta_generic_to_shared(p);
}
__device__ __forceinline__ void ldmx4(unsigned* r, unsigned addr) {
    asm volatile(
        "ldmatrix.sync.aligned.m8n8.x4.shared.b16 {%0,%1,%2,%3}, [%4];"
        : "=r"(r[0]), "=r"(r[1]), "=r"(r[2]), "=r"(r[3]) : "r"(addr));
}
__device__ __forceinline__ void ldmx4t(unsigned* r, unsigned addr) {
    asm volatile(
        "ldmatrix.sync.aligned.m8n8.x4.trans.shared.b16 {%0,%1,%2,%3}, [%4];"
        : "=r"(r[0]), "=r"(r[1]), "=r"(r[2]), "=r"(r[3]) : "r"(addr));
}
__device__ __forceinline__ void mma_f16(float* d, const unsigned* a,
                                        unsigned b0, unsigned b1) {
    asm volatile(
        "mma.sync.aligned.m16n8k16.row.col.f32.f16.f16.f32 "
        "{%0,%1,%2,%3}, {%4,%5,%6,%7}, {%8,%9}, {%0,%1,%2,%3};"
        : "+f"(d[0]), "+f"(d[1]), "+f"(d[2]), "+f"(d[3])
        : "r"(a[0]), "r"(a[1]), "r"(a[2]), "r"(a[3]), "r"(b0), "r"(b1));
}

// fp32 pair -> fp16x2 (lo half = x0)
__device__ __forceinline__ unsigned pack_f16(float x0, float x1) {
    unsigned r;
    asm("cvt.rn.f16x2.f32 %0, %1, %2;" : "=r"(r) : "f"(x1), "f"(x0));
    return r;
}

// cp.async 16B (bypass-L1)
__device__ __forceinline__ void cp_async16(void* smem_ptr, const void* gptr) {
    unsigned saddr = (unsigned)__cvta_generic_to_shared(smem_ptr);
    asm volatile("cp.async.cg.shared.global [%0], [%1], 16;"
                 :: "r"(saddr), "l"(gptr) : "memory");
}
__device__ __forceinline__ void cp_commit() {
    asm volatile("cp.async.commit_group;" ::: "memory");
}
__device__ __forceinline__ void cp_wait0() {
    asm volatile("cp.async.wait_group 0;" ::: "memory");
}
__device__ __forceinline__ void cp_wait1() {
    asm volatile("cp.async.wait_group 1;" ::: "memory");
}

// ---------------------------------------------------------------------------
// Weight prep: all four weights -> fp16
// ---------------------------------------------------------------------------
__global__ void __launch_bounds__(256)
presplit_w(const float* __restrict__ w0, const float* __restrict__ w1,
           const float* __restrict__ w2, const float* __restrict__ w3) {
    const int m = blockIdx.y;
    const float* src = (m == 0) ? w0 : (m == 1) ? w1 : (m == 2) ? w2 : w3;
    const int gid = blockIdx.x * 256 + threadIdx.x;   // 0..131071
    const float4* s4 = (const float4*)src;
    float4 a = s4[2 * gid], b = s4[2 * gid + 1];
    uint4 f;
    f.x = pack_f16(a.x, a.y);
    f.y = pack_f16(a.z, a.w);
    f.z = pack_f16(b.x, b.y);
    f.w = pack_f16(b.z, b.w);
    ((uint4*)g_Wf)[(size_t)m * WU4 + gid] = f;
}

// ---------------------------------------------------------------------------
// fp16 single-MMA NT GEMM: C[m,n] = sum_k A[m,k]*W[n,k].
// CTA 128x128, 512 threads, 16 warps (4x4, warp 32x32), K staged 64/stage,
// cp.async double-buffered. PA: A fp16 pre-made (pure cp.async); else fp32
// converted in-loop. F16OUT: C -> fp16 scratch; else fp32 out.
// ---------------------------------------------------------------------------
#define GF_TILE_BYTES (128 * 64 * 2)            // 16 KB (f16 tile)
#define GF_BUF_BYTES (2 * GF_TILE_BYTES)        // A + B = 32 KB
#define GEMMF_SMEM (2 * GF_BUF_BYTES + 1024)
#define GK_STAGES 16

template <bool PA, bool F16OUT>
__device__ __forceinline__ void gemm_f16_body(
    const float* __restrict__ A, const unsigned* __restrict__ Af,
    const unsigned* __restrict__ Wf,
    float* __restrict__ C, unsigned* __restrict__ Cf) {
    extern __shared__ char dyn_raw[];
    char* dynb = (char*)(((unsigned long long)(size_t)dyn_raw + 1023ull) &
                         ~1023ull);
    const unsigned sbase = smem_u32(dynb);

    const int tid = threadIdx.x;
    const int wid = tid >> 5;
    const int lane = tid & 31;
    const int m0 = blockIdx.y * 128;
    const int n0 = blockIdx.x * 128;

    const float4* A4 = (const float4*)A;

    const int rb = tid >> 3;      // 0..63
    const int cc = tid & 7;

    const int wm = (wid >> 2) * 32;
    const int wn = (wid & 3) * 32;
    const int arow = lane & 15;
    const unsigned ahi = (unsigned)(lane >> 4);
    const unsigned axor = (unsigned)((arow & 7) << 4);
    const int brow = (lane & 7) + ((lane >> 4) << 3);
    const unsigned bxor = (unsigned)((brow & 7) << 4);
    const unsigned bhi = (unsigned)((lane >> 3) & 1);

    float d[2][4][4];
#pragma unroll
    for (int i = 0; i < 2; i++)
#pragma unroll
        for (int j = 0; j < 4; j++)
#pragma unroll
            for (int e = 0; e < 4; e++) d[i][j][e] = 0.0f;

    float4 ra[2][2];

#define FBUF(b) (dynb + (b) * GF_BUF_BYTES)

#define GF_LDGA(s)                                                         \
    do { if (!PA) {                                                        \
        _Pragma("unroll")                                                  \
        for (int i = 0; i < 2; i++) {                                      \
            const size_t ga =                                              \
                (size_t)(m0 + rb + 64 * i) * 256 + (s) * 16 + cc * 2;      \
            ra[i][0] = A4[ga];                                             \
            ra[i][1] = A4[ga + 1];                                         \
        } } } while (0)

#define GF_STSA(b)                                                         \
    do { if (!PA) {                                                        \
        char* Ap = FBUF(b);                                                \
        _Pragma("unroll")                                                  \
        for (int i = 0; i < 2; i++) {                                      \
            const int r = rb + 64 * i;                                     \
            const unsigned sw = (unsigned)(r * 128) +                      \
                (((unsigned)cc ^ (unsigned)(r & 7)) << 4);                 \
            uint4 f;                                                       \
            f.x = pack_f16(ra[i][0].x, ra[i][0].y);                        \
            f.y = pack_f16(ra[i][0].z, ra[i][0].w);                        \
            f.z = pack_f16(ra[i][1].x, ra[i][1].y);                        \
            f.w = pack_f16(ra[i][1].z, ra[i][1].w);                        \
            *(uint4*)(Ap + sw) = f;                                        \
        } } } while (0)

#define GF_CPA(s, b)                                                       \
    do { if (PA) {                                                         \
        _Pragma("unroll")                                                  \
        for (int i = 0; i < 2; i++) {                                      \
            const int idx = tid + 512 * i;                                 \
            const int r2 = idx >> 3, c2 = idx & 7;                         \
            cp_async16(FBUF(b) + r2 * 128 +                                \
                           (((unsigned)c2 ^ (unsigned)(r2 & 7)) << 4),     \
                       Af + (size_t)(m0 + r2) * DM2 + (s) * 32 + c2 * 4);  \
        } } } while (0)

#define GF_CPB(s, b)                                                       \
    do {                                                                   \
        _Pragma("unroll")                                                  \
        for (int i = 0; i < 2; i++) {                                      \
            const int idx = tid + 512 * i;                                 \
            const int r2 = idx >> 3, c2 = idx & 7;                         \
            cp_async16(FBUF(b) + GF_TILE_BYTES + r2 * 128 +                \
                           (((unsigned)c2 ^ (unsigned)(r2 & 7)) << 4),     \
                       Wf + (size_t)(n0 + r2) * DM2 + (s) * 32 + c2 * 4);  \
        } } while (0)

    GF_LDGA(0);
    GF_CPA(0, 0);
    GF_CPB(0, 0);
    cp_commit();
    GF_STSA(0);
    GF_LDGA(1);

    for (int s = 0; s < GK_STAGES; s++) {
        const int cur = s & 1;
        if (s + 1 < GK_STAGES) {
            GF_CPA(s + 1, cur ^ 1);
            GF_CPB(s + 1, cur ^ 1);
            cp_commit();
            GF_STSA(cur ^ 1);
            if (s + 2 < GK_STAGES) GF_LDGA(s + 2);
            cp_wait1();
        } else {
            cp_wait0();
        }
        __syncthreads();

        const unsigned bo = sbase + (unsigned)cur * GF_BUF_BYTES;
        const unsigned sA = bo;
        const unsigned sB = bo + GF_TILE_BYTES;
#pragma unroll
        for (int ks = 0; ks < 4; ks++) {
            unsigned bf[2][4];
#pragma unroll
            for (int j2 = 0; j2 < 2; j2++) {
                const unsigned roff =
                    (unsigned)(wn + 16 * j2 + brow) * 128 +
                    ((((unsigned)(2 * ks) + bhi) << 4) ^ bxor);
                ldmx4(bf[j2], sB + roff);
            }
#pragma unroll
            for (int i = 0; i < 2; i++) {
                const unsigned aoff =
                    (unsigned)(wm + 16 * i + arow) * 128 +
                    ((((unsigned)(2 * ks) + ahi) << 4) ^ axor);
                unsigned af[4];
                ldmx4(af, sA + aoff);
#pragma unroll
                for (int j = 0; j < 4; j++)
                    mma_f16(d[i][j], af, bf[j >> 1][(j & 1) * 2],
                            bf[j >> 1][(j & 1) * 2 + 1]);
            }
        }
        __syncthreads();
    }
#undef GF_LDGA
#undef GF_STSA
#undef GF_CPA
#undef GF_CPB
#undef FBUF

    // ---- epilogue ----
    const int r0 = m0 + wm + (lane >> 2);
    const int cb = n0 + wn + 2 * (lane & 3);
    if (F16OUT) {
#pragma unroll
        for (int i = 0; i < 2; i++)
#pragma unroll
            for (int j = 0; j < 4; j++) {
                const unsigned p0 = pack_f16(d[i][j][0], d[i][j][1]);
                const unsigned p1 = pack_f16(d[i][j][2], d[i][j][3]);
                const size_t idx =
                    (size_t)(r0 + 16 * i) * DM2 + (cb >> 1) + 4 * j;
                Cf[idx] = p0;
                Cf[idx + 8 * DM2] = p1;
            }
    } else {
        float* Cbase = C + (size_t)r0 * DMODEL + cb;
#pragma unroll
        for (int i = 0; i < 2; i++)
#pragma unroll
            for (int j = 0; j < 4; j++) {
                *(float2*)(Cbase + (size_t)(16 * i) * DMODEL + 8 * j) =
                    make_float2(d[i][j][0], d[i][j][1]);
                *(float2*)(Cbase + (size_t)(16 * i + 8) * DMODEL + 8 * j) =
                    make_float2(d[i][j][2], d[i][j][3]);
            }
    }
}

__global__ void __launch_bounds__(512, 1)
mha_gemm_qkv_f16(const float* __restrict__ q, const float* __restrict__ k,
                 const float* __restrict__ v) {
    const int z = blockIdx.z;
    const float* A = (z == 0) ? q : (z == 1) ? k : v;
    const unsigned* Wf = g_Wf + (size_t)z * DMODEL * DM2;
    unsigned* Cf = (z == 0) ? g_Qf : (z == 1) ? g_Kf : g_Vf;
    gemm_f16_body<false, true>(A, nullptr, Wf, nullptr, Cf);
}

__global__ void __launch_bounds__(512, 1)
mha_gemm_out_f16(float* __restrict__ out) {
    const unsigned* Wf = g_Wf + (size_t)3 * DMODEL * DM2;
    gemm_f16_body<true, false>(nullptr, g_Xf, Wf, out, nullptr);
}

// ---------------------------------------------------------------------------
// fp16 single-pass tensor-core flash attention.
// __launch_bounds__(256, 2): cap regs at 128 -> 2 CTAs/SM (16 warps) to hide
// the QK->softmax->PV latency chain. Softmax in exp2 domain: scores pre-
// scaled by 0.125*log2(e) so exp2f is a single MUFU on the critical path.
// ---------------------------------------------------------------------------
#define ATT_BM 128
#define ATT_BN 64
#define ATT_TILE_B (ATT_BN * 128)            // 8 KB: 64 rows x 128B fp16
#define ATT_BUF_B (2 * ATT_TILE_B)           // Kf + Vf = 16 KB per buffer
#define ATT_SMEM (2 * ATT_BUF_B + 1024)      // ~33 KB
#define ATT_SC 0.1803368801111204f           // 0.125 * log2(e)

__global__ void __launch_bounds__(256, 2)
mha_flash_attn_tc(const int* __restrict__ mask) {
    extern __shared__ char att_raw[];
    char* base = (char*)(((unsigned long long)(size_t)att_raw + 1023ull) &
                         ~1023ull);
    const unsigned sbase = smem_u32(base);

    const int tid = threadIdx.x;
    const int wid = tid >> 5;
    const int lane = tid & 31;
    const int q0 = blockIdx.x * ATT_BM;
    const int bh = blockIdx.y;
    const int b = bh >> 4;
    const int h = bh & 15;

    // ---- prologue: K/V tile 0 -> buf0; Q -> buf1 region ----
#pragma unroll
    for (int i = 0; i < 4; i++) {
        const int idx = tid + 256 * i;
        const int t = idx >> 9;                 // 0: K, 1: V
        const int idx2 = idx & 511;
        const int r = idx2 >> 3, cc = idx2 & 7;
        const unsigned* src = t ? g_Vf : g_Kf;
        const size_t gi = (size_t)(b * SEQ + r) * DM2 + h * 32 + cc * 4;
        char* dst = base + t * ATT_TILE_B + r * 128 + ((cc ^ (r & 7)) << 4);
        cp_async16(dst, src + gi);
    }
#pragma unroll
    for (int i = 0; i < 4; i++) {
        const int idx = tid + 256 * i;
        const int r = idx >> 3, cc = idx & 7;
        const size_t gi = (size_t)(b * SEQ + q0 + r) * DM2 + h * 32 + cc * 4;
        char* dst = base + ATT_BUF_B + r * 128 + ((cc ^ (r & 7)) << 4);
        cp_async16(dst, g_Qf + gi);
    }
    cp_commit();
    cp_wait0();
    __syncthreads();

    // ---- Q fragments (registers, whole kernel) ----
    unsigned qf[4][4];
    {
        const int arow = lane & 15;
        const unsigned ahi = (unsigned)(lane >> 4);
        const int row = 16 * wid + arow;
#pragma unroll
        for (int kk = 0; kk < 4; kk++) {
            const unsigned ch = 2 * (unsigned)kk + ahi;
            const unsigned off =
                (unsigned)(row * 128) + ((ch ^ (unsigned)(row & 7)) << 4);
            ldmx4(qf[kk], sbase + ATT_BUF_B + off);
        }
    }
    __syncthreads();

    float o[8][4];
#pragma unroll
    for (int j = 0; j < 8; j++)
#pragma unroll
        for (int e = 0; e < 4; e++) o[j][e] = 0.0f;
    float m0 = -1e30f, m1 = -1e30f, l0 = 0.0f, l1 = 0.0f;

    const int grow = q0 + 16 * wid + (lane >> 2);
    const int* mrow0 = mask + ((size_t)b * SEQ + grow) * SEQ;
    const int* mrow1 = mrow0 + 8 * SEQ;

    const int brow = (lane & 7) + ((lane >> 4) << 3);
    const unsigned bxor = (unsigned)((brow & 7) << 4);
    const unsigned bhi = (unsigned)((lane >> 3) & 1);
    const int vtt = lane >> 3;
    const int vrow_lo = ((vtt & 1) << 3) + (lane & 7);
    const unsigned vch_add = (unsigned)(vtt >> 1);

    for (int n = 0; n < SEQ / ATT_BN; n++) {
        const int j0 = n * ATT_BN;
        const int cur = n & 1;
        if (n > 0) {
            cp_wait0();
            __syncthreads();
        }
        if (n + 1 < SEQ / ATT_BN) {
            char* bufn = base + (cur ^ 1) * ATT_BUF_B;
            const int jn = j0 + ATT_BN;
#pragma unroll
            for (int i = 0; i < 4; i++) {
                const int idx = tid + 256 * i;
                const int t = idx >> 9;
                const int idx2 = idx & 511;
                const int r = idx2 >> 3, cc = idx2 & 7;
                const unsigned* src = t ? g_Vf : g_Kf;
                const size_t gi =
                    (size_t)(b * SEQ + jn + r) * DM2 + h * 32 + cc * 4;
                char* dst =
                    bufn + t * ATT_TILE_B + r * 128 + ((cc ^ (r & 7)) << 4);
                cp_async16(dst, src + gi);
            }
            cp_commit();
        }

        const unsigned sKf = sbase + (unsigned)cur * ATT_BUF_B;
        const unsigned sVf = sKf + ATT_TILE_B;

        // ---- S = Q.K^T ----
        float c[8][4];
#pragma unroll
        for (int j = 0; j < 8; j++)
#pragma unroll
            for (int e = 0; e < 4; e++) c[j][e] = 0.0f;

#pragma unroll
        for (int ks = 0; ks < 4; ks++) {
#pragma unroll
            for (int j2 = 0; j2 < 4; j2++) {
                const int kr = 16 * j2 + brow;
                const unsigned off = (unsigned)(kr * 128) +
                    ((((unsigned)(2 * ks) + bhi) << 4) ^ bxor);
                unsigned kb[4];
                ldmx4(kb, sKf + off);
                mma_f16(c[2 * j2],     qf[ks], kb[0], kb[1]);
                mma_f16(c[2 * j2 + 1], qf[ks], kb[2], kb[3]);
            }
        }

        // ---- scale (exp2 domain) + mask ----
        const int mcol = j0 + 2 * (lane & 3);
#pragma unroll
        for (int j = 0; j < 8; j++) {
            const int2 mv0 = *(const int2*)(mrow0 + mcol + 8 * j);
            const int2 mv1 = *(const int2*)(mrow1 + mcol + 8 * j);
            c[j][0] = mv0.x ? c[j][0] * ATT_SC : -1e9f;
            c[j][1] = mv0.y ? c[j][1] * ATT_SC : -1e9f;
            c[j][2] = mv1.x ? c[j][2] * ATT_SC : -1e9f;
            c[j][3] = mv1.y ? c[j][3] * ATT_SC : -1e9f;
        }

        // ---- row max ----
        float t0 = -1e30f, t1 = -1e30f;
#pragma unroll
        for (int j = 0; j < 8; j++) {
            t0 = fmaxf(t0, fmaxf(c[j][0], c[j][1]));
            t1 = fmaxf(t1, fmaxf(c[j][2], c[j][3]));
        }
        t0 = fmaxf(t0, __shfl_xor_sync(0xffffffffu, t0, 1));
        t0 = fmaxf(t0, __shfl_xor_sync(0xffffffffu, t0, 2));
        t1 = fmaxf(t1, __shfl_xor_sync(0xffffffffu, t1, 1));
        t1 = fmaxf(t1, __shfl_xor_sync(0xffffffffu, t1, 2));

        const float mn0 = fmaxf(m0, t0);
        const float mn1 = fmaxf(m1, t1);
        const float al0 = exp2f(m0 - mn0);
        const float al1 = exp2f(m1 - mn1);
        m0 = mn0; m1 = mn1;
        l0 *= al0; l1 *= al1;
#pragma unroll
        for (int j = 0; j < 8; j++) {
            o[j][0] *= al0; o[j][1] *= al0;
            o[j][2] *= al1; o[j][3] *= al1;
        }

        // ---- exponentiate (single MUFU each) ----
#pragma unroll
        for (int j = 0; j < 8; j++) {
            c[j][0] = exp2f(c[j][0] - m0);
            c[j][1] = exp2f(c[j][1] - m0);
            c[j][2] = exp2f(c[j][2] - m1);
            c[j][3] = exp2f(c[j][3] - m1);
            l0 += c[j][0] + c[j][1];
            l1 += c[j][2] + c[j][3];
        }

        // ---- O += P.V ----
#pragma unroll
        for (int kk = 0; kk < 4; kk++) {
            unsigned paf[4];
            paf[0] = pack_f16(c[2 * kk][0],     c[2 * kk][1]);
            paf[1] = pack_f16(c[2 * kk][2],     c[2 * kk][3]);
            paf[2] = pack_f16(c[2 * kk + 1][0], c[2 * kk + 1][1]);
            paf[3] = pack_f16(c[2 * kk + 1][2], c[2 * kk + 1][3]);
#pragma unroll
            for (int j2 = 0; j2 < 4; j2++) {
                const int vr = 16 * kk + vrow_lo;
                const unsigned ch = 2 * (unsigned)j2 + vch_add;
                const unsigned off = (unsigned)(vr * 128) +
                    ((ch ^ (unsigned)(vr & 7)) << 4);
                unsigned vb[4];
                ldmx4t(vb, sVf + off);
                mma_f16(o[2 * j2],     paf, vb[0], vb[1]);
                mma_f16(o[2 * j2 + 1], paf, vb[2], vb[3]);
            }
        }
    }

    // ---- finalize: normalize, write X as fp16 ----
    l0 += __shfl_xor_sync(0xffffffffu, l0, 1);
    l0 += __shfl_xor_sync(0xffffffffu, l0, 2);
    l1 += __shfl_xor_sync(0xffffffffu, l1, 1);
    l1 += __shfl_xor_sync(0xffffffffu, l1, 2);
    const float inv0 = 1.0f / l0;
    const float inv1 = 1.0f / l1;

    const size_t xrow = (size_t)(b * SEQ + grow) * DM2 + h * 32 + (lane & 3);
#pragma unroll
    for (int j = 0; j < 8; j++) {
        g_Xf[xrow + 4 * j] = pack_f16(o[j][0] * inv0, o[j][1] * inv0);
        g_Xf[xrow + 8 * DM2 + 4 * j] = pack_f16(o[j][2] * inv1, o[j][3] * inv1);
    }
}

// ---------------------------------------------------------------------------
// Launch
// Inputs (metadata order): q, k, v, w_q, w_k, w_v, w_o, mask
// ---------------------------------------------------------------------------
extern "C" void kernel_launch(void* const* d_in, const int* in_sizes, int n_in,
                              void* d_out, int out_size) {
    const float* q  = (const float*)d_in[0];
    const float* k  = (const float*)d_in[1];
    const float* v  = (const float*)d_in[2];
    const float* wq = (const float*)d_in[3];
    const float* wk = (const float*)d_in[4];
    const float* wv = (const float*)d_in[5];
    const float* wo = (const float*)d_in[6];
    const int* mask = (const int*)d_in[7];
    float* out = (float*)d_out;

    cudaFuncSetAttribute(mha_gemm_qkv_f16,
                         cudaFuncAttributeMaxDynamicSharedMemorySize,
                         GEMMF_SMEM);
    cudaFuncSetAttribute(mha_gemm_out_f16,
                         cudaFuncAttributeMaxDynamicSharedMemorySize,
                         GEMMF_SMEM);
    cudaFuncSetAttribute(mha_flash_attn_tc,
                         cudaFuncAttributeMaxDynamicSharedMemorySize, ATT_SMEM);

    // 0) weight prep: all four weights -> fp16
    dim3 gw(512, 4);
    presplit_w<<<gw, 256>>>(wq, wk, wv, wo);

    // 1) Q/K/V projections: fp16 single-MMA
    dim3 gqkv(DMODEL / 128, MROWS / 128, 3);
    mha_gemm_qkv_f16<<<gqkv, 512, GEMMF_SMEM>>>(q, k, v);

    // 2) fp16 flash attention (writes X fp16)
    dim3 gatt(SEQ / ATT_BM, BATCH * NHEAD);
    mha_flash_attn_tc<<<gatt, 256, ATT_SMEM>>>(mask);

    // 3) output projection: fp16 single-MMA
    dim3 gout(DMODEL / 128, MROWS / 128, 1);
    mha_gemm_out_f16<<<gout, 512, GEMMF_SMEM>>>(out);
}